// round 4
// baseline (speedup 1.0000x reference)
#include <cuda_runtime.h>
#include <math.h>

// Problem constants (fixed by the reference config)
#define Mm 8
#define Bb 4096
#define Tt 33
#define Dd 8
#define FFf 28
#define Rr 3
#define NPp 8         // (m,b) pairs per block; each thread handles 2 (p, p+4)
#define TPB 160       // 4*33 = 132 active threads, each owning 2 tokens
#define EPSf 1e-5f
#define ATT_SCALE 0.3535533905932738f  // 1/sqrt(8)
#define INV_SQRT2 0.7071067811865476f

typedef unsigned long long u64;

__device__ __forceinline__ u64 pk(float lo, float hi) {
    u64 r; asm("mov.b64 %0, {%1, %2};" : "=l"(r) : "f"(lo), "f"(hi)); return r;
}
__device__ __forceinline__ void unpk(float& lo, float& hi, u64 v) {
    asm("mov.b64 {%0, %1}, %2;" : "=f"(lo), "=f"(hi) : "l"(v));
}
// d = a*b + d   (packed 2xfp32, Blackwell)
__device__ __forceinline__ void fma2(u64& d, u64 a, u64 b) {
    asm("fma.rn.f32x2 %0, %1, %2, %0;" : "+l"(d) : "l"(a), "l"(b));
}

// packed dot of 8 floats: a pre-packed as 4 u64, w = 16B-aligned smem row
__device__ __forceinline__ float dot8p(const u64* a4, const float* __restrict__ w) {
    const ulonglong2* wp = reinterpret_cast<const ulonglong2*>(w);
    ulonglong2 w01 = wp[0], w23 = wp[1];
    u64 acc = 0ULL;
    fma2(acc, a4[0], w01.x);
    fma2(acc, a4[1], w01.y);
    fma2(acc, a4[2], w23.x);
    fma2(acc, a4[3], w23.y);
    float lo, hi; unpk(lo, hi, acc);
    return lo + hi;
}

__global__ __launch_bounds__(TPB)
void fused_block_kernel(
    const float* __restrict__ gx,
    const float* __restrict__ gln1w, const float* __restrict__ gln1b,
    const float* __restrict__ gqkvw, const float* __restrict__ gprojw,
    const float* __restrict__ gln2w, const float* __restrict__ gln2b,
    const float* __restrict__ gfc1A, const float* __restrict__ gfc1B,
    const float* __restrict__ gfc1Wf,
    const float* __restrict__ gfc2A, const float* __restrict__ gfc2B,
    const float* __restrict__ gfc2Wf,
    float* __restrict__ gout)
{
    __shared__ __align__(16) float s_qkvT[24][Dd];   // q:0-7 k:8-15 v:16-23
    __shared__ __align__(16) float s_projT[Dd][Dd];
    __shared__ __align__(16) float s_w1T[FFf][Dd];   // fc1_A@fc1_B + fc1_Wf
    __shared__ __align__(16) float s_w2T[Dd][FFf];   // fc2_A@fc2_B + fc2_Wf
    __shared__ __align__(16) float s_ln[4][Dd];
    // KV: [pair][token][k0..7 v0..7]; warp-uniform row reads are broadcast,
    // the two pair-groups per warp land on disjoint bank groups.
    __shared__ __align__(16) float s_kv[NPp][Tt][16];

    const int tid = threadIdx.x;
    const int m  = blockIdx.x / (Bb / NPp);
    const int bc = blockIdx.x % (Bb / NPp);

    // ---- cooperative weight staging (collapse low-rank terms once) ----
    for (int idx = tid; idx < Dd * 24; idx += TPB) {
        int i = idx / 24, o = idx % 24;
        s_qkvT[o][i] = gqkvw[(m * Dd + i) * 24 + o];
    }
    for (int idx = tid; idx < Dd * Dd; idx += TPB) {
        int i = idx >> 3, o = idx & 7;
        s_projT[o][i] = gprojw[(m * Dd + i) * Dd + o];
    }
    for (int idx = tid; idx < Dd * FFf; idx += TPB) {
        int i = idx / FFf, o = idx % FFf;
        float acc = gfc1Wf[(m * Dd + i) * FFf + o];
        #pragma unroll
        for (int r = 0; r < Rr; r++)
            acc = fmaf(gfc1A[(m * Dd + i) * Rr + r],
                       gfc1B[(m * Rr + r) * FFf + o], acc);
        s_w1T[o][i] = acc;
    }
    for (int idx = tid; idx < FFf * Dd; idx += TPB) {
        int f = idx >> 3, o = idx & 7;
        float acc = gfc2Wf[(m * FFf + f) * Dd + o];
        #pragma unroll
        for (int r = 0; r < Rr; r++)
            acc = fmaf(gfc2A[(m * FFf + f) * Rr + r],
                       gfc2B[(m * Rr + r) * Dd + o], acc);
        s_w2T[o][f] = acc;
    }
    if (tid < Dd) {
        s_ln[0][tid] = gln1w[m * Dd + tid];
        s_ln[1][tid] = gln1b[m * Dd + tid];
        s_ln[2][tid] = gln2w[m * Dd + tid];
        s_ln[3][tid] = gln2b[m * Dd + tid];
    }
    __syncthreads();

    const bool active = (tid < (NPp / 2) * Tt);
    const int p = tid / Tt;            // 0..3; streams use p and p+4
    const int t = tid - p * Tt;

    float xr[2][8];
    u64 qp[2][4];
    long base[2];
    #pragma unroll
    for (int s = 0; s < 2; s++) {
        int b = bc * NPp + p + 4 * s;
        base[s] = ((((long)m * Bb + b) * Tt) + t) * Dd;
    }

    if (active) {
        #pragma unroll
        for (int s = 0; s < 2; s++) {
            float4 a0 = *reinterpret_cast<const float4*>(gx + base[s]);
            float4 a1 = *reinterpret_cast<const float4*>(gx + base[s] + 4);
            xr[s][0] = a0.x; xr[s][1] = a0.y; xr[s][2] = a0.z; xr[s][3] = a0.w;
            xr[s][4] = a1.x; xr[s][5] = a1.y; xr[s][6] = a1.z; xr[s][7] = a1.w;
        }

        #pragma unroll
        for (int s = 0; s < 2; s++) {
            // LayerNorm 1
            float mean = 0.f;
            #pragma unroll
            for (int i = 0; i < 8; i++) mean += xr[s][i];
            mean *= 0.125f;
            float var = 0.f;
            #pragma unroll
            for (int i = 0; i < 8; i++) { float d = xr[s][i] - mean; var = fmaf(d, d, var); }
            var *= 0.125f;
            float rstd = rsqrtf(var + EPSf);
            float h[8];
            #pragma unroll
            for (int i = 0; i < 8; i++)
                h[i] = fmaf((xr[s][i] - mean) * rstd, s_ln[0][i], s_ln[1][i]);

            u64 hp[4];
            #pragma unroll
            for (int i = 0; i < 4; i++) hp[i] = pk(h[2 * i], h[2 * i + 1]);

            #pragma unroll
            for (int i = 0; i < 4; i++)
                qp[s][i] = pk(dot8p(hp, &s_qkvT[2 * i][0]) * ATT_SCALE,
                              dot8p(hp, &s_qkvT[2 * i + 1][0]) * ATT_SCALE);
            float* kvp = &s_kv[p + 4 * s][t][0];
            #pragma unroll
            for (int o = 0; o < 8; o += 4) {
                float4 kk = make_float4(dot8p(hp, &s_qkvT[8 + o][0]),
                                        dot8p(hp, &s_qkvT[9 + o][0]),
                                        dot8p(hp, &s_qkvT[10 + o][0]),
                                        dot8p(hp, &s_qkvT[11 + o][0]));
                *reinterpret_cast<float4*>(kvp + o) = kk;
            }
            #pragma unroll
            for (int o = 0; o < 8; o += 4) {
                float4 vv = make_float4(dot8p(hp, &s_qkvT[16 + o][0]),
                                        dot8p(hp, &s_qkvT[17 + o][0]),
                                        dot8p(hp, &s_qkvT[18 + o][0]),
                                        dot8p(hp, &s_qkvT[19 + o][0]));
                *reinterpret_cast<float4*>(kvp + 8 + o) = vv;
            }
        }
    }
    __syncthreads();

    if (active) {
        // ---- causal attention, both streams in one loop (2x ILP).
        // Scores are O(0.03): softmax without max-shift is exact. ----
        const ulonglong2* kvA = reinterpret_cast<const ulonglong2*>(&s_kv[p][0][0]);
        const ulonglong2* kvB = reinterpret_cast<const ulonglong2*>(&s_kv[p + 4][0][0]);
        u64 yA[4] = {0ULL, 0ULL, 0ULL, 0ULL};
        u64 yB[4] = {0ULL, 0ULL, 0ULL, 0ULL};
        float sumA = 0.f, sumB = 0.f;
        for (int j = 0; j <= t; j++) {
            ulonglong2 ka01 = kvA[0], ka23 = kvA[1];
            ulonglong2 va01 = kvA[2], va23 = kvA[3];
            ulonglong2 kb01 = kvB[0], kb23 = kvB[1];
            ulonglong2 vb01 = kvB[2], vb23 = kvB[3];
            kvA += 4; kvB += 4;
            u64 accA = 0ULL, accB = 0ULL;
            fma2(accA, qp[0][0], ka01.x);
            fma2(accB, qp[1][0], kb01.x);
            fma2(accA, qp[0][1], ka01.y);
            fma2(accB, qp[1][1], kb01.y);
            fma2(accA, qp[0][2], ka23.x);
            fma2(accB, qp[1][2], kb23.x);
            fma2(accA, qp[0][3], ka23.y);
            fma2(accB, qp[1][3], kb23.y);
            float la, ha, lb, hb;
            unpk(la, ha, accA);
            unpk(lb, hb, accB);
            float eA = __expf(la + ha);
            float eB = __expf(lb + hb);
            sumA += eA; sumB += eB;
            u64 eeA = pk(eA, eA), eeB = pk(eB, eB);
            fma2(yA[0], eeA, va01.x);
            fma2(yB[0], eeB, vb01.x);
            fma2(yA[1], eeA, va01.y);
            fma2(yB[1], eeB, vb01.y);
            fma2(yA[2], eeA, va23.x);
            fma2(yB[2], eeB, vb23.x);
            fma2(yA[3], eeA, va23.y);
            fma2(yB[3], eeB, vb23.y);
        }
        float invA = 1.f / sumA, invB = 1.f / sumB;

        #pragma unroll
        for (int s = 0; s < 2; s++) {
            u64* yy = s ? yB : yA;
            float inv = s ? invB : invA;
            float y[8];
            unpk(y[0], y[1], yy[0]); unpk(y[2], y[3], yy[1]);
            unpk(y[4], y[5], yy[2]); unpk(y[6], y[7], yy[3]);
            u64 yp[4];
            #pragma unroll
            for (int i = 0; i < 4; i++)
                yp[i] = pk(y[2 * i] * inv, y[2 * i + 1] * inv);

            // output projection + residual
            #pragma unroll
            for (int o = 0; o < 8; o++) xr[s][o] += dot8p(yp, &s_projT[o][0]);

            // LayerNorm 2
            float mean = 0.f;
            #pragma unroll
            for (int i = 0; i < 8; i++) mean += xr[s][i];
            mean *= 0.125f;
            float var = 0.f;
            #pragma unroll
            for (int i = 0; i < 8; i++) { float d = xr[s][i] - mean; var = fmaf(d, d, var); }
            var *= 0.125f;
            float rstd = rsqrtf(var + EPSf);
            u64 h2p[4];
            #pragma unroll
            for (int i = 0; i < 4; i++) {
                float e0 = fmaf((xr[s][2 * i]     - mean) * rstd, s_ln[2][2 * i],     s_ln[3][2 * i]);
                float e1 = fmaf((xr[s][2 * i + 1] - mean) * rstd, s_ln[2][2 * i + 1], s_ln[3][2 * i + 1]);
                h2p[i] = pk(e0, e1);
            }

            // fc1 (collapsed weights) + exact-erf GELU
            u64 gp[FFf / 2];
            #pragma unroll
            for (int o = 0; o < FFf; o += 2) {
                float u0 = dot8p(h2p, &s_w1T[o][0]);
                float u1 = dot8p(h2p, &s_w1T[o + 1][0]);
                float g0 = 0.5f * u0 * (1.f + erff(u0 * INV_SQRT2));
                float g1 = 0.5f * u1 * (1.f + erff(u1 * INV_SQRT2));
                gp[o >> 1] = pk(g0, g1);
            }

            // fc2 (collapsed weights) + residual
            #pragma unroll
            for (int o = 0; o < 8; o++) {
                const ulonglong2* wp = reinterpret_cast<const ulonglong2*>(&s_w2T[o][0]);
                u64 acc = 0ULL;
                #pragma unroll
                for (int f = 0; f < 7; f++) {
                    ulonglong2 w2 = wp[f];
                    fma2(acc, gp[2 * f],     w2.x);
                    fma2(acc, gp[2 * f + 1], w2.y);
                }
                float lo, hi; unpk(lo, hi, acc);
                xr[s][o] += lo + hi;
            }

            float4 r0 = make_float4(xr[s][0], xr[s][1], xr[s][2], xr[s][3]);
            float4 r1 = make_float4(xr[s][4], xr[s][5], xr[s][6], xr[s][7]);
            *reinterpret_cast<float4*>(gout + base[s])     = r0;
            *reinterpret_cast<float4*>(gout + base[s] + 4) = r1;
        }
    }
}

extern "C" void kernel_launch(void* const* d_in, const int* in_sizes, int n_in,
                              void* d_out, int out_size) {
    (void)in_sizes; (void)n_in; (void)out_size;
    const float* x      = (const float*)d_in[0];
    const float* ln1w   = (const float*)d_in[1];
    const float* ln1b   = (const float*)d_in[2];
    const float* qkvw   = (const float*)d_in[3];
    const float* projw  = (const float*)d_in[4];
    const float* ln2w   = (const float*)d_in[5];
    const float* ln2b   = (const float*)d_in[6];
    const float* fc1A   = (const float*)d_in[7];
    const float* fc1B   = (const float*)d_in[8];
    const float* fc1Wf  = (const float*)d_in[9];
    const float* fc2A   = (const float*)d_in[10];
    const float* fc2B   = (const float*)d_in[11];
    const float* fc2Wf  = (const float*)d_in[12];
    float* out = (float*)d_out;

    dim3 grid(Mm * (Bb / NPp));
    dim3 block(TPB);
    fused_block_kernel<<<grid, block>>>(
        x, ln1w, ln1b, qkvw, projw, ln2w, ln2b,
        fc1A, fc1B, fc1Wf, fc2A, fc2B, fc2Wf, out);
}